// round 15
// baseline (speedup 1.0000x reference)
#include <cuda_runtime.h>
#include <cuda_bf16.h>
#include <cstdint>
#include <math.h>

#define B_  1024
#define N_  1024
#define M_  128
#define C_  1024
#define OUTF 390
#define EPS 1e-16f
#define KSPLIT 8
#define KCHUNK (C_ / KSPLIT)   // 128
#define KSTEPS (KCHUNK / 16)   // 8 k16-steps per block

// ---------------- scratch ----------------
__device__ float g_part[KSPLIT * B_ * OUTF];
__device__ float g_o[B_ * OUTF];     // (k|beta|g|s0..2|gamma|e|a), e sigmoided
__device__ float g_scal[B_ * 8];     // beta,g,gamma,knorm,s0,s1,s2

// ---------------- K1: split-K GEMM via bf16-split tensor cores ----------------
// D = Ahi*Bhi + Ahi*Blo + Alo*Bhi  (fp32 accum; error ~2^-16 relative)
// 64x64 tile, 256 threads (8 warps: 4 row-groups x 2 col-halves),
// per warp per k16-step: 4 n-tiles x 3 mma.m16n8k16.
__global__ void __launch_bounds__(256)
k1_gemm(const float* __restrict__ A,
        const float* __restrict__ Bm)
{
    __shared__ __nv_bfloat16 sAhi[64][16];
    __shared__ __nv_bfloat16 sAlo[64][16];
    __shared__ __nv_bfloat16 sBhi[64][16];   // [col][k]  (col-major for B frags)
    __shared__ __nv_bfloat16 sBlo[64][16];

    const int tid  = threadIdx.x;
    const int warp = tid >> 5;
    const int lane = tid & 31;
    const int rg   = warp & 3;        // row group: rows 16*rg..
    const int ch   = warp >> 2;       // col half:  cols 32*ch..
    const int g    = lane >> 2;       // 0..7
    const int tq   = lane & 3;        // 0..3

    const int row0 = blockIdx.y * 64;
    const int col0 = blockIdx.x * 64;
    const int kbeg = blockIdx.z * KCHUNK;

    // fill mappings
    const int far = tid >> 2;           // A row 0..63
    const int fac = (tid & 3) * 4;      // A k base 0,4,8,12
    const int fbk = tid >> 4;           // B k row 0..15
    const int fbc = (tid & 15) * 4;     // B col base 0..60

    float acc[4][4];
#pragma unroll
    for (int i = 0; i < 4; i++)
#pragma unroll
        for (int j = 0; j < 4; j++) acc[i][j] = 0.f;

    for (int t = 0; t < KSTEPS; t++) {
        const int k0 = kbeg + t * 16;

        // ---- fill A: 64x16 fp32 -> hi/lo bf16 ----
        {
            const float4 av = *(const float4*)&A[(size_t)(row0 + far) * C_ + k0 + fac];
            float v[4] = {av.x, av.y, av.z, av.w};
            __nv_bfloat16 hi[4], lo[4];
#pragma unroll
            for (int j = 0; j < 4; j++) {
                hi[j] = __float2bfloat16_rn(v[j]);
                lo[j] = __float2bfloat16_rn(v[j] - __bfloat162float(hi[j]));
            }
            __nv_bfloat162 h01; h01.x = hi[0]; h01.y = hi[1];
            __nv_bfloat162 h23; h23.x = hi[2]; h23.y = hi[3];
            __nv_bfloat162 l01; l01.x = lo[0]; l01.y = lo[1];
            __nv_bfloat162 l23; l23.x = lo[2]; l23.y = lo[3];
            *(__nv_bfloat162*)&sAhi[far][fac]     = h01;
            *(__nv_bfloat162*)&sAhi[far][fac + 2] = h23;
            *(__nv_bfloat162*)&sAlo[far][fac]     = l01;
            *(__nv_bfloat162*)&sAlo[far][fac + 2] = l23;
        }
        // ---- fill B: 16x64 fp32 -> hi/lo bf16, stored [col][k] ----
        {
            const float* bsrc = &Bm[(size_t)(k0 + fbk) * OUTF + col0 + fbc];
#pragma unroll
            for (int j = 0; j < 4; j++) {
                float v = (col0 + fbc + j < OUTF) ? bsrc[j] : 0.f;
                __nv_bfloat16 hi = __float2bfloat16_rn(v);
                __nv_bfloat16 lo = __float2bfloat16_rn(v - __bfloat162float(hi));
                sBhi[fbc + j][fbk] = hi;
                sBlo[fbc + j][fbk] = lo;
            }
        }
        __syncthreads();

        // ---- A fragments (m16n8k16 row-major) ----
        const int arow = rg * 16 + g;
        uint32_t ah0 = *(const uint32_t*)&sAhi[arow][2 * tq];
        uint32_t ah1 = *(const uint32_t*)&sAhi[arow + 8][2 * tq];
        uint32_t ah2 = *(const uint32_t*)&sAhi[arow][2 * tq + 8];
        uint32_t ah3 = *(const uint32_t*)&sAhi[arow + 8][2 * tq + 8];
        uint32_t al0 = *(const uint32_t*)&sAlo[arow][2 * tq];
        uint32_t al1 = *(const uint32_t*)&sAlo[arow + 8][2 * tq];
        uint32_t al2 = *(const uint32_t*)&sAlo[arow][2 * tq + 8];
        uint32_t al3 = *(const uint32_t*)&sAlo[arow + 8][2 * tq + 8];

#pragma unroll
        for (int nt = 0; nt < 4; nt++) {
            const int ncol = ch * 32 + nt * 8 + g;
            uint32_t bh0 = *(const uint32_t*)&sBhi[ncol][2 * tq];
            uint32_t bh1 = *(const uint32_t*)&sBhi[ncol][2 * tq + 8];
            uint32_t bl0 = *(const uint32_t*)&sBlo[ncol][2 * tq];
            uint32_t bl1 = *(const uint32_t*)&sBlo[ncol][2 * tq + 8];
            float* c = acc[nt];
            asm volatile(
                "mma.sync.aligned.m16n8k16.row.col.f32.bf16.bf16.f32 "
                "{%0,%1,%2,%3}, {%4,%5,%6,%7}, {%8,%9}, {%0,%1,%2,%3};"
                : "+f"(c[0]), "+f"(c[1]), "+f"(c[2]), "+f"(c[3])
                : "r"(ah0), "r"(ah1), "r"(ah2), "r"(ah3), "r"(bh0), "r"(bh1));
            asm volatile(
                "mma.sync.aligned.m16n8k16.row.col.f32.bf16.bf16.f32 "
                "{%0,%1,%2,%3}, {%4,%5,%6,%7}, {%8,%9}, {%0,%1,%2,%3};"
                : "+f"(c[0]), "+f"(c[1]), "+f"(c[2]), "+f"(c[3])
                : "r"(ah0), "r"(ah1), "r"(ah2), "r"(ah3), "r"(bl0), "r"(bl1));
            asm volatile(
                "mma.sync.aligned.m16n8k16.row.col.f32.bf16.bf16.f32 "
                "{%0,%1,%2,%3}, {%4,%5,%6,%7}, {%8,%9}, {%0,%1,%2,%3};"
                : "+f"(c[0]), "+f"(c[1]), "+f"(c[2]), "+f"(c[3])
                : "r"(al0), "r"(al1), "r"(al2), "r"(al3), "r"(bh0), "r"(bh1));
        }
        __syncthreads();
    }

    // ---- writeback (D fragment: c0=[g][2t], c1=[g][2t+1], c2=[g+8][2t], c3=[g+8][2t+1]) ----
    float* part = &g_part[(size_t)blockIdx.z * B_ * OUTF];
    const int wrow0 = row0 + rg * 16 + g;
#pragma unroll
    for (int nt = 0; nt < 4; nt++) {
        const int c0 = col0 + ch * 32 + nt * 8 + 2 * tq;
        if (c0 < OUTF) {
            part[(size_t)wrow0 * OUTF + c0]       = acc[nt][0];
            part[(size_t)(wrow0 + 8) * OUTF + c0] = acc[nt][2];
        }
        if (c0 + 1 < OUTF) {
            part[(size_t)wrow0 * OUTF + c0 + 1]       = acc[nt][1];
            part[(size_t)(wrow0 + 8) * OUTF + c0 + 1] = acc[nt][3];
        }
    }
}

// ---------------- K2: fused split-K reduce + bias + activations ----------------
__device__ __forceinline__ float softplus_f(float x) {
    return (x > 0.f) ? (x + log1pf(expf(-x))) : log1pf(expf(x));
}
__device__ __forceinline__ float sigmoid_f(float x) {
    return 1.f / (1.f + expf(-x));
}

__global__ void k2_redact(const float* __restrict__ bias)  // grid=B_, block=256
{
    const int b   = blockIdx.x;
    const int tid = threadIdx.x;
    __shared__ float so[OUTF];
    __shared__ float red[8];

    for (int col = tid; col < OUTF; col += 256) {
        float s = bias[col];
#pragma unroll
        for (int ks = 0; ks < KSPLIT; ks++)
            s += g_part[(size_t)ks * B_ * OUTF + (size_t)b * OUTF + col];
        so[col] = s;
    }
    __syncthreads();

    float ss = 0.f;
    if (tid < 128) { float kv = so[tid]; ss = kv * kv; }
#pragma unroll
    for (int off = 16; off > 0; off >>= 1)
        ss += __shfl_xor_sync(0xffffffffu, ss, off);
    if ((tid & 31) == 0) red[tid >> 5] = ss;
    __syncthreads();

    if (tid == 0) {
        float knorm = sqrtf(red[0] + red[1] + red[2] + red[3]);
        float beta  = softplus_f(so[M_]);
        float g     = sigmoid_f(so[M_ + 1]);
        float s0 = so[M_ + 2], s1 = so[M_ + 3], s2 = so[M_ + 4];
        float mx = fmaxf(s0, fmaxf(s1, s2));
        float e0 = expf(s0 - mx), e1 = expf(s1 - mx), e2 = expf(s2 - mx);
        float es = e0 + e1 + e2;
        float gamma = 1.f + softplus_f(so[M_ + 5]);
        float* sc = &g_scal[b * 8];
        sc[0] = beta; sc[1] = g; sc[2] = gamma; sc[3] = knorm;
        sc[4] = e0 / es; sc[5] = e1 / es; sc[6] = e2 / es;
    }

    float* o = &g_o[(size_t)b * OUTF];
    for (int col = tid; col < OUTF; col += 256) {
        float v = so[col];
        if (col >= M_ + 6 && col < 2 * M_ + 6) v = sigmoid_f(v);
        o[col] = v;
    }
}

// ---------------- KF: fused sim + weighting + update (unchanged, proven) ----------------
__global__ void __launch_bounds__(1024, 1)
kF_fused(const float* __restrict__ mem,
         const float* __restrict__ w_prev,
         float* __restrict__ w_out,
         float* __restrict__ out_mem)
{
    extern __shared__ float sh[];
    float* sk   = sh;            // 128
    float* se   = sk + 128;      // 128
    float* sa   = se + 128;      // 128
    float* slog = sa + 128;      // 1024
    float* warr = slog + 1024;   // 1024
    float* sred = warr + 1024;   // 32

    const int b    = blockIdx.x;
    const int tid  = threadIdx.x;
    const int warp = tid >> 5;
    const int lane = tid & 31;

    if (tid < 128) {
        sk[tid] = g_o[(size_t)b * OUTF + tid];
        se[tid] = g_o[(size_t)b * OUTF + M_ + 6 + tid];
        sa[tid] = g_o[(size_t)b * OUTF + 2 * M_ + 6 + tid];
    }
    __syncthreads();

    const float beta  = g_scal[b * 8 + 0];
    const float g     = g_scal[b * 8 + 1];
    const float gamma = g_scal[b * 8 + 2];
    const float knorm = g_scal[b * 8 + 3];
    const float s0    = g_scal[b * 8 + 4];
    const float s1    = g_scal[b * 8 + 5];
    const float s2    = g_scal[b * 8 + 6];

    const float* memb = mem + (size_t)b * N_ * M_;

    // ---- pass 1: 8 lanes per row ----
    const int sub = lane >> 3;          // 0..3
    const int qc  = (lane & 7) * 4;     // 0..28
    float kq[4][4];
#pragma unroll
    for (int q = 0; q < 4; q++) {
        const float4 kv = *(const float4*)&sk[qc + 32 * q];
        kq[q][0] = kv.x; kq[q][1] = kv.y; kq[q][2] = kv.z; kq[q][3] = kv.w;
    }

#pragma unroll
    for (int i0 = 0; i0 < 32; i0 += 8) {
        const int n0 = warp * 32 + i0 + sub;
        const int n1 = n0 + 4;
        float4 mv0[4], mv1[4];
#pragma unroll
        for (int q = 0; q < 4; q++) {
            mv0[q] = *(const float4*)&memb[(size_t)n0 * M_ + qc + 32 * q];
            mv1[q] = *(const float4*)&memb[(size_t)n1 * M_ + qc + 32 * q];
        }
        float dot0 = 0.f, ssq0 = 0.f, dot1 = 0.f, ssq1 = 0.f;
#pragma unroll
        for (int q = 0; q < 4; q++) {
            dot0 = fmaf(mv0[q].x, kq[q][0], dot0); ssq0 = fmaf(mv0[q].x, mv0[q].x, ssq0);
            dot0 = fmaf(mv0[q].y, kq[q][1], dot0); ssq0 = fmaf(mv0[q].y, mv0[q].y, ssq0);
            dot0 = fmaf(mv0[q].z, kq[q][2], dot0); ssq0 = fmaf(mv0[q].z, mv0[q].z, ssq0);
            dot0 = fmaf(mv0[q].w, kq[q][3], dot0); ssq0 = fmaf(mv0[q].w, mv0[q].w, ssq0);
            dot1 = fmaf(mv1[q].x, kq[q][0], dot1); ssq1 = fmaf(mv1[q].x, mv1[q].x, ssq1);
            dot1 = fmaf(mv1[q].y, kq[q][1], dot1); ssq1 = fmaf(mv1[q].y, mv1[q].y, ssq1);
            dot1 = fmaf(mv1[q].z, kq[q][2], dot1); ssq1 = fmaf(mv1[q].z, mv1[q].z, ssq1);
            dot1 = fmaf(mv1[q].w, kq[q][3], dot1); ssq1 = fmaf(mv1[q].w, mv1[q].w, ssq1);
        }
#pragma unroll
        for (int off = 4; off > 0; off >>= 1) {
            dot0 += __shfl_xor_sync(0xffffffffu, dot0, off);
            ssq0 += __shfl_xor_sync(0xffffffffu, ssq0, off);
            dot1 += __shfl_xor_sync(0xffffffffu, dot1, off);
            ssq1 += __shfl_xor_sync(0xffffffffu, ssq1, off);
        }
        if ((lane & 7) == 0) {
            slog[n0] = beta * (dot0 / (sqrtf(ssq0) * knorm + EPS));
            slog[n1] = beta * (dot1 / (sqrtf(ssq1) * knorm + EPS));
        }
    }
    __syncthreads();

    // ---- softmax -> gate -> shift -> sharpen ----
    float x = slog[tid];
    float lmax = x;
#pragma unroll
    for (int off = 16; off > 0; off >>= 1)
        lmax = fmaxf(lmax, __shfl_xor_sync(0xffffffffu, lmax, off));
    if (lane == 0) sred[warp] = lmax;
    __syncthreads();
    float bmax = sred[0];
#pragma unroll
    for (int k = 1; k < 32; k++) bmax = fmaxf(bmax, sred[k]);

    float p = expf(x - bmax);
    float lsum = p;
#pragma unroll
    for (int off = 16; off > 0; off >>= 1)
        lsum += __shfl_xor_sync(0xffffffffu, lsum, off);
    __syncthreads();
    if (lane == 0) sred[warp] = lsum;
    __syncthreads();
    float bsum = 0.f;
#pragma unroll
    for (int k = 0; k < 32; k++) bsum += sred[k];
    const float inv = 1.f / bsum;

    slog[tid] = g * (p * inv) + (1.f - g) * w_prev[(size_t)b * N_ + tid];
    __syncthreads();

    float wt = s0 * slog[(tid + N_ - 1) & (N_ - 1)] + s1 * slog[tid]
             + s2 * slog[(tid + 1) & (N_ - 1)];
    float wpow = powf(wt + EPS, gamma);
    float lsum2 = wpow;
#pragma unroll
    for (int off = 16; off > 0; off >>= 1)
        lsum2 += __shfl_xor_sync(0xffffffffu, lsum2, off);
    __syncthreads();
    if (lane == 0) sred[warp] = lsum2;
    __syncthreads();
    float bsum2 = 0.f;
#pragma unroll
    for (int k = 0; k < 32; k++) bsum2 += sred[k];
    const float inv2 = 1.f / (bsum2 + EPS);

    const float wv = wpow * inv2;
    warr[tid] = wv;
    w_out[(size_t)b * N_ + tid] = wv;
    __syncthreads();

    // ---- pass 2: 8 rows in flight; reads are L2 hits ----
    const float4 ev = *(const float4*)&se[lane * 4];
    const float4 av = *(const float4*)&sa[lane * 4];
    float* outb = out_mem + (size_t)b * N_ * M_;
#pragma unroll
    for (int i0 = 0; i0 < 32; i0 += 8) {
        const int nbase = warp * 32 + i0;
        float4 mv[8];
        float wr[8];
#pragma unroll
        for (int i = 0; i < 8; i++) {
            mv[i] = __ldcs((const float4*)&memb[(size_t)(nbase + i) * M_ + lane * 4]);
            wr[i] = warr[nbase + i];
        }
#pragma unroll
        for (int i = 0; i < 8; i++) {
            float4 r;
            r.x = mv[i].x * (1.f - wr[i] * ev.x) + wr[i] * av.x;
            r.y = mv[i].y * (1.f - wr[i] * ev.y) + wr[i] * av.y;
            r.z = mv[i].z * (1.f - wr[i] * ev.z) + wr[i] * av.z;
            r.w = mv[i].w * (1.f - wr[i] * ev.w) + wr[i] * av.w;
            __stcs((float4*)&outb[(size_t)(nbase + i) * M_ + lane * 4], r);
        }
    }
}

// ---------------- launch ----------------
extern "C" void kernel_launch(void* const* d_in, const int* in_sizes, int n_in,
                              void* d_out, int out_size)
{
    const float* emb    = (const float*)d_in[0];
    const float* w_prev = (const float*)d_in[1];
    const float* mem    = (const float*)d_in[2];
    const float* fc_w   = (const float*)d_in[3];
    const float* fc_b   = (const float*)d_in[4];

    float* out_w   = (float*)d_out;
    float* out_mem = out_w + (size_t)B_ * N_;

    dim3 g1((OUTF + 63) / 64, B_ / 64, KSPLIT);
    k1_gemm<<<g1, 256>>>(emb, fc_w);
    k2_redact<<<B_, 256>>>(fc_b);

    const int smemF = 120 * 1024;   // force 1 CTA/SM (L2 residency)
    cudaFuncSetAttribute(kF_fused, cudaFuncAttributeMaxDynamicSharedMemorySize, smemF);
    kF_fused<<<B_, 1024, smemF>>>(mem, w_prev, out_w, out_mem);
}

// round 16
// speedup vs baseline: 1.0852x; 1.0852x over previous
#include <cuda_runtime.h>
#include <cstdint>
#include <math.h>

#define B_  1024
#define N_  1024
#define M_  128
#define C_  1024
#define OUTF 390
#define EPS 1e-16f
#define KSPLIT 8
#define KCHUNK (C_ / KSPLIT)   // 128
#define KSTEPS (KCHUNK / 16)   // 8 k16-steps per block

// ---------------- scratch ----------------
__device__ float g_part[KSPLIT * B_ * OUTF];
__device__ float g_o[B_ * OUTF];     // (k|beta|g|s0..2|gamma|e|a), e sigmoided
__device__ float g_scal[B_ * 8];     // beta,g,gamma,knorm,s0,s1,s2

// ---------------- tf32 split helpers ----------------
__device__ __forceinline__ void split_tf32(float x, uint32_t& hi, uint32_t& lo) {
    asm("cvt.rna.tf32.f32 %0, %1;" : "=r"(hi) : "f"(x));
    float r = x - __uint_as_float(hi);
    asm("cvt.rna.tf32.f32 %0, %1;" : "=r"(lo) : "f"(r));
}
__device__ __forceinline__ void mma_tf32(float* c, const uint32_t* a, uint32_t b0, uint32_t b1) {
    asm volatile(
        "mma.sync.aligned.m16n8k8.row.col.f32.tf32.tf32.f32 "
        "{%0,%1,%2,%3}, {%4,%5,%6,%7}, {%8,%9}, {%0,%1,%2,%3};"
        : "+f"(c[0]), "+f"(c[1]), "+f"(c[2]), "+f"(c[3])
        : "r"(a[0]), "r"(a[1]), "r"(a[2]), "r"(a[3]), "r"(b0), "r"(b1));
}

// ---------------- K1: split-K GEMM via tf32-split tensor cores ----------------
// D = Ahi*Bhi + Ahi*Blo + Alo*Bhi  (error ~2^-22 relative)
// 64x64 tile, 256 threads (8 warps: 4 row-groups x 2 col-halves)
__global__ void __launch_bounds__(256)
k1_gemm(const float* __restrict__ A,
        const float* __restrict__ Bm)
{
    __shared__ __align__(16) float sA[64][20];   // [row][k], pad 20 (conflict-free frags)
    __shared__ __align__(16) float sB[16][68];   // [k][col],  pad 68

    const int tid  = threadIdx.x;
    const int warp = tid >> 5;
    const int lane = tid & 31;
    const int rg   = warp & 3;        // rows 16*rg..
    const int ch   = warp >> 2;       // cols 32*ch..
    const int g    = lane >> 2;       // 0..7
    const int tq   = lane & 3;        // 0..3

    const int row0 = blockIdx.y * 64;
    const int col0 = blockIdx.x * 64;
    const int kbeg = blockIdx.z * KCHUNK;

    // fill mappings
    const int far = tid >> 2;           // A row 0..63
    const int fac = (tid & 3) * 4;      // A k base
    const int fbk = tid >> 4;           // B k row 0..15
    const int fbc = (tid & 15) * 4;     // B col base
    const bool btail = (col0 + 64 > OUTF);

    float acc[4][4];
#pragma unroll
    for (int i = 0; i < 4; i++)
#pragma unroll
        for (int j = 0; j < 4; j++) acc[i][j] = 0.f;

    const int arow = rg * 16 + g;

    for (int t = 0; t < KSTEPS; t++) {
        const int k0 = kbeg + t * 16;

        // ---- fill A: float4 in, float4 out ----
        {
            const float4 av = *(const float4*)&A[(size_t)(row0 + far) * C_ + k0 + fac];
            *(float4*)&sA[far][fac] = av;
        }
        // ---- fill B: 16x64 fp32, [k][col] ----
        {
            const float* bsrc = &Bm[(size_t)(k0 + fbk) * OUTF + col0 + fbc];
            float4 bv;
            if (!btail) {
                const float2 b01 = *(const float2*)bsrc;
                const float2 b23 = *(const float2*)(bsrc + 2);
                bv.x = b01.x; bv.y = b01.y; bv.z = b23.x; bv.w = b23.y;
            } else {
                bv.x = (col0 + fbc + 0 < OUTF) ? bsrc[0] : 0.f;
                bv.y = (col0 + fbc + 1 < OUTF) ? bsrc[1] : 0.f;
                bv.z = (col0 + fbc + 2 < OUTF) ? bsrc[2] : 0.f;
                bv.w = (col0 + fbc + 3 < OUTF) ? bsrc[3] : 0.f;
            }
            *(float4*)&sB[fbk][fbc] = bv;
        }
        __syncthreads();

#pragma unroll
        for (int h = 0; h < 2; h++) {          // two k8 halves of this k16
            const int kb = h * 8;
            // A fragment (m16n8k8, row-major): hi/lo
            float a_f[4];
            a_f[0] = sA[arow][kb + tq];
            a_f[1] = sA[arow + 8][kb + tq];
            a_f[2] = sA[arow][kb + tq + 4];
            a_f[3] = sA[arow + 8][kb + tq + 4];
            uint32_t ahi[4], alo[4];
#pragma unroll
            for (int i = 0; i < 4; i++) split_tf32(a_f[i], ahi[i], alo[i]);

#pragma unroll
            for (int nt = 0; nt < 4; nt++) {
                const int ncol = ch * 32 + nt * 8 + g;
                float b0f = sB[kb + tq][ncol];
                float b1f = sB[kb + tq + 4][ncol];
                uint32_t bh0, bl0, bh1, bl1;
                split_tf32(b0f, bh0, bl0);
                split_tf32(b1f, bh1, bl1);
                mma_tf32(acc[nt], ahi, bh0, bh1);   // hi*hi
                mma_tf32(acc[nt], ahi, bl0, bl1);   // hi*lo
                mma_tf32(acc[nt], alo, bh0, bh1);   // lo*hi
            }
        }
        __syncthreads();
    }

    // ---- writeback (m16n8 D frag: c0=[g][2tq], c1=[g][2tq+1], c2=[g+8][2tq], c3=[g+8][2tq+1]) ----
    float* part = &g_part[(size_t)blockIdx.z * B_ * OUTF];
    const int wrow0 = row0 + rg * 16 + g;
#pragma unroll
    for (int nt = 0; nt < 4; nt++) {
        const int c0 = col0 + ch * 32 + nt * 8 + 2 * tq;
        if (c0 < OUTF) {
            part[(size_t)wrow0 * OUTF + c0]       = acc[nt][0];
            part[(size_t)(wrow0 + 8) * OUTF + c0] = acc[nt][2];
        }
        if (c0 + 1 < OUTF) {
            part[(size_t)wrow0 * OUTF + c0 + 1]       = acc[nt][1];
            part[(size_t)(wrow0 + 8) * OUTF + c0 + 1] = acc[nt][3];
        }
    }
}

// ---------------- K2: fused split-K reduce + bias + activations ----------------
__device__ __forceinline__ float softplus_f(float x) {
    return (x > 0.f) ? (x + log1pf(expf(-x))) : log1pf(expf(x));
}
__device__ __forceinline__ float sigmoid_f(float x) {
    return 1.f / (1.f + expf(-x));
}

__global__ void k2_redact(const float* __restrict__ bias)  // grid=B_, block=256
{
    const int b   = blockIdx.x;
    const int tid = threadIdx.x;
    __shared__ float so[OUTF];
    __shared__ float red[8];

    for (int col = tid; col < OUTF; col += 256) {
        float s = bias[col];
#pragma unroll
        for (int ks = 0; ks < KSPLIT; ks++)
            s += g_part[(size_t)ks * B_ * OUTF + (size_t)b * OUTF + col];
        so[col] = s;
    }
    __syncthreads();

    float ss = 0.f;
    if (tid < 128) { float kv = so[tid]; ss = kv * kv; }
#pragma unroll
    for (int off = 16; off > 0; off >>= 1)
        ss += __shfl_xor_sync(0xffffffffu, ss, off);
    if ((tid & 31) == 0) red[tid >> 5] = ss;
    __syncthreads();

    if (tid == 0) {
        float knorm = sqrtf(red[0] + red[1] + red[2] + red[3]);
        float beta  = softplus_f(so[M_]);
        float g     = sigmoid_f(so[M_ + 1]);
        float s0 = so[M_ + 2], s1 = so[M_ + 3], s2 = so[M_ + 4];
        float mx = fmaxf(s0, fmaxf(s1, s2));
        float e0 = expf(s0 - mx), e1 = expf(s1 - mx), e2 = expf(s2 - mx);
        float es = e0 + e1 + e2;
        float gamma = 1.f + softplus_f(so[M_ + 5]);
        float* sc = &g_scal[b * 8];
        sc[0] = beta; sc[1] = g; sc[2] = gamma; sc[3] = knorm;
        sc[4] = e0 / es; sc[5] = e1 / es; sc[6] = e2 / es;
    }

    float* o = &g_o[(size_t)b * OUTF];
    for (int col = tid; col < OUTF; col += 256) {
        float v = so[col];
        if (col >= M_ + 6 && col < 2 * M_ + 6) v = sigmoid_f(v);
        o[col] = v;
    }
}

// ---------------- KF: fused sim + weighting + update (unchanged, proven) ----------------
__global__ void __launch_bounds__(1024, 1)
kF_fused(const float* __restrict__ mem,
         const float* __restrict__ w_prev,
         float* __restrict__ w_out,
         float* __restrict__ out_mem)
{
    extern __shared__ float sh[];
    float* sk   = sh;            // 128
    float* se   = sk + 128;      // 128
    float* sa   = se + 128;      // 128
    float* slog = sa + 128;      // 1024
    float* warr = slog + 1024;   // 1024
    float* sred = warr + 1024;   // 32

    const int b    = blockIdx.x;
    const int tid  = threadIdx.x;
    const int warp = tid >> 5;
    const int lane = tid & 31;

    if (tid < 128) {
        sk[tid] = g_o[(size_t)b * OUTF + tid];
        se[tid] = g_o[(size_t)b * OUTF + M_ + 6 + tid];
        sa[tid] = g_o[(size_t)b * OUTF + 2 * M_ + 6 + tid];
    }
    __syncthreads();

    const float beta  = g_scal[b * 8 + 0];
    const float g     = g_scal[b * 8 + 1];
    const float gamma = g_scal[b * 8 + 2];
    const float knorm = g_scal[b * 8 + 3];
    const float s0    = g_scal[b * 8 + 4];
    const float s1    = g_scal[b * 8 + 5];
    const float s2    = g_scal[b * 8 + 6];

    const float* memb = mem + (size_t)b * N_ * M_;

    // ---- pass 1: 8 lanes per row ----
    const int sub = lane >> 3;          // 0..3
    const int qc  = (lane & 7) * 4;     // 0..28
    float kq[4][4];
#pragma unroll
    for (int q = 0; q < 4; q++) {
        const float4 kv = *(const float4*)&sk[qc + 32 * q];
        kq[q][0] = kv.x; kq[q][1] = kv.y; kq[q][2] = kv.z; kq[q][3] = kv.w;
    }

#pragma unroll
    for (int i0 = 0; i0 < 32; i0 += 8) {
        const int n0 = warp * 32 + i0 + sub;
        const int n1 = n0 + 4;
        float4 mv0[4], mv1[4];
#pragma unroll
        for (int q = 0; q < 4; q++) {
            mv0[q] = *(const float4*)&memb[(size_t)n0 * M_ + qc + 32 * q];
            mv1[q] = *(const float4*)&memb[(size_t)n1 * M_ + qc + 32 * q];
        }
        float dot0 = 0.f, ssq0 = 0.f, dot1 = 0.f, ssq1 = 0.f;
#pragma unroll
        for (int q = 0; q < 4; q++) {
            dot0 = fmaf(mv0[q].x, kq[q][0], dot0); ssq0 = fmaf(mv0[q].x, mv0[q].x, ssq0);
            dot0 = fmaf(mv0[q].y, kq[q][1], dot0); ssq0 = fmaf(mv0[q].y, mv0[q].y, ssq0);
            dot0 = fmaf(mv0[q].z, kq[q][2], dot0); ssq0 = fmaf(mv0[q].z, mv0[q].z, ssq0);
            dot0 = fmaf(mv0[q].w, kq[q][3], dot0); ssq0 = fmaf(mv0[q].w, mv0[q].w, ssq0);
            dot1 = fmaf(mv1[q].x, kq[q][0], dot1); ssq1 = fmaf(mv1[q].x, mv1[q].x, ssq1);
            dot1 = fmaf(mv1[q].y, kq[q][1], dot1); ssq1 = fmaf(mv1[q].y, mv1[q].y, ssq1);
            dot1 = fmaf(mv1[q].z, kq[q][2], dot1); ssq1 = fmaf(mv1[q].z, mv1[q].z, ssq1);
            dot1 = fmaf(mv1[q].w, kq[q][3], dot1); ssq1 = fmaf(mv1[q].w, mv1[q].w, ssq1);
        }
#pragma unroll
        for (int off = 4; off > 0; off >>= 1) {
            dot0 += __shfl_xor_sync(0xffffffffu, dot0, off);
            ssq0 += __shfl_xor_sync(0xffffffffu, ssq0, off);
            dot1 += __shfl_xor_sync(0xffffffffu, dot1, off);
            ssq1 += __shfl_xor_sync(0xffffffffu, ssq1, off);
        }
        if ((lane & 7) == 0) {
            slog[n0] = beta * (dot0 / (sqrtf(ssq0) * knorm + EPS));
            slog[n1] = beta * (dot1 / (sqrtf(ssq1) * knorm + EPS));
        }
    }
    __syncthreads();

    // ---- softmax -> gate -> shift -> sharpen ----
    float x = slog[tid];
    float lmax = x;
#pragma unroll
    for (int off = 16; off > 0; off >>= 1)
        lmax = fmaxf(lmax, __shfl_xor_sync(0xffffffffu, lmax, off));
    if (lane == 0) sred[warp] = lmax;
    __syncthreads();
    float bmax = sred[0];
#pragma unroll
    for (int k = 1; k < 32; k++) bmax = fmaxf(bmax, sred[k]);

    float p = expf(x - bmax);
    float lsum = p;
#pragma unroll
    for (int off = 16; off > 0; off >>= 1)
        lsum += __shfl_xor_sync(0xffffffffu, lsum, off);
    __syncthreads();
    if (lane == 0) sred[warp] = lsum;
    __syncthreads();
    float bsum = 0.f;
#pragma unroll
    for (int k = 0; k < 32; k++) bsum += sred[k];
    const float inv = 1.f / bsum;

    slog[tid] = g * (p * inv) + (1.f - g) * w_prev[(size_t)b * N_ + tid];
    __syncthreads();

    float wt = s0 * slog[(tid + N_ - 1) & (N_ - 1)] + s1 * slog[tid]
             + s2 * slog[(tid + 1) & (N_ - 1)];
    float wpow = powf(wt + EPS, gamma);
    float lsum2 = wpow;
#pragma unroll
    for (int off = 16; off > 0; off >>= 1)
        lsum2 += __shfl_xor_sync(0xffffffffu, lsum2, off);
    __syncthreads();
    if (lane == 0) sred[warp] = lsum2;
    __syncthreads();
    float bsum2 = 0.f;
#pragma unroll
    for (int k = 0; k < 32; k++) bsum2 += sred[k];
    const float inv2 = 1.f / (bsum2 + EPS);

    const float wv = wpow * inv2;
    warr[tid] = wv;
    w_out[(size_t)b * N_ + tid] = wv;
    __syncthreads();

    // ---- pass 2: 8 rows in flight; reads are L2 hits ----
    const float4 ev = *(const float4*)&se[lane * 4];
    const float4 av = *(const float4*)&sa[lane * 4];
    float* outb = out_mem + (size_t)b * N_ * M_;
#pragma unroll
    for (int i0 = 0; i0 < 32; i0 += 8) {
        const int nbase = warp * 32 + i0;
        float4 mv[8];
        float wr[8];
#pragma unroll
        for (int i = 0; i < 8; i++) {
            mv[i] = __ldcs((const float4*)&memb[(size_t)(nbase + i) * M_ + lane * 4]);
            wr[i] = warr[nbase + i];
        }
#pragma unroll
        for (int i = 0; i < 8; i++) {
            float4 r;
            r.x = mv[i].x * (1.f - wr[i] * ev.x) + wr[i] * av.x;
            r.y = mv[i].y * (1.f - wr[i] * ev.y) + wr[i] * av.y;
            r.z = mv[i].z * (1.f - wr[i] * ev.z) + wr[i] * av.z;
            r.w = mv[i].w * (1.f - wr[i] * ev.w) + wr[i] * av.w;
            __stcs((float4*)&outb[(size_t)(nbase + i) * M_ + lane * 4], r);
        }
    }
}

// ---------------- launch ----------------
extern "C" void kernel_launch(void* const* d_in, const int* in_sizes, int n_in,
                              void* d_out, int out_size)
{
    const float* emb    = (const float*)d_in[0];
    const float* w_prev = (const float*)d_in[1];
    const float* mem    = (const float*)d_in[2];
    const float* fc_w   = (const float*)d_in[3];
    const float* fc_b   = (const float*)d_in[4];

    float* out_w   = (float*)d_out;
    float* out_mem = out_w + (size_t)B_ * N_;

    dim3 g1((OUTF + 63) / 64, B_ / 64, KSPLIT);
    k1_gemm<<<g1, 256>>>(emb, fc_w);
    k2_redact<<<B_, 256>>>(fc_b);

    const int smemF = 120 * 1024;   // force 1 CTA/SM (L2 residency)
    cudaFuncSetAttribute(kF_fused, cudaFuncAttributeMaxDynamicSharedMemorySize, smemF);
    kF_fused<<<B_, 1024, smemF>>>(mem, w_prev, out_w, out_mem);
}